// round 3
// baseline (speedup 1.0000x reference)
#include <cuda_runtime.h>
#include <cstdint>

// ---------------- problem constants ----------------
#define NB 4
#define NC 512
#define NG 2048
#define OC 64
#define NBAS 10
#define NPT 8192                           // NB*NG flat points
#define EPSV 1e-6f
#define BN_EPS 1e-5f

// output layout (float32, concatenated in return order)
#define OFF_Y   0                          // (4,2048,64)
#define OFF_NF  524288                     // (4,2048,9)
#define OFF_FP  598016                     // (4,2048,3,3)
#define OFF_NH1 671744                     // (4,2048,3,3)
#define OFF_H0  745472                     // (4,2048,9)

// scratch (device globals). SoA: [chan][b][g]
__device__ float g_pos[9 * NPT];
__device__ float g_conv[9 * NPT];
__device__ float g_stats[18];
__device__ unsigned g_barcnt = 0;
__device__ volatile unsigned g_sense = 0;

// ---------------- dynamic SMEM layout (floats) ----------------
// sdat   : 4 batches * 512 * 8   = 16384   (swizzled {x,y} context)
// swT    : 18*64                 = 1152
// sbias  : 64
// ssw    : 4*30 = 120
// ssb    : 120
// srw    : 12 (10+pad)
// scoef  : 4  (3+pad)
// sstat  : 20 (18+pad)
// sgam   : 12, sbet : 12
// sfeat  : 32*19 = 608
// then doubles: ss[256], sq[256]
#define F_SDAT   0
#define F_SWT    16384
#define F_SBIAS  (F_SWT + 1152)
#define F_SSW    (F_SBIAS + 64)
#define F_SSB    (F_SSW + 120)
#define F_SRW    (F_SSB + 120)
#define F_SCOEF  (F_SRW + 12)
#define F_SSTAT  (F_SCOEF + 4)
#define F_SGAM   (F_SSTAT + 20)
#define F_SBET   (F_SGAM + 12)
#define F_SFEAT  (F_SBET + 12)
#define F_TOTAL  (F_SFEAT + 608)          // 18508 floats = 74032 B (8B aligned)
#define SMEM_BYTES (F_TOTAL * 4 + 512 * 8)

__device__ __forceinline__ float ex2f(float x) {
    float y;
    asm("ex2.approx.ftz.f32 %0, %1;" : "=f"(y) : "f"(x));
    return y;
}

// sense-reversing grid barrier (all blocks co-resident by construction)
__device__ __forceinline__ void gridbar() {
    __syncthreads();
    if (threadIdx.x == 0) {
        unsigned s = g_sense;
        __threadfence();
        if (atomicAdd(&g_barcnt, 1u) == gridDim.x - 1) {
            g_barcnt = 0;
            __threadfence();
            g_sense = s + 1;
        } else {
            while (g_sense == s) { }
        }
        __threadfence();
    }
    __syncthreads();
}

__global__ void __launch_bounds__(256, 1)
fused_all(const float* __restrict__ xc, const float* __restrict__ yc,
          const float* __restrict__ xg, const float* __restrict__ sigma,
          const float* __restrict__ mu, const float* __restrict__ eps1,
          const float* __restrict__ bu, const float* __restrict__ rw,
          const float* __restrict__ w1, const float* __restrict__ b1,
          const float* __restrict__ w2, const float* __restrict__ b2,
          const float* __restrict__ w3, const float* __restrict__ b3,
          const float* __restrict__ gamma, const float* __restrict__ beta,
          const float* __restrict__ gw, const float* __restrict__ gb,
          float* __restrict__ out)
{
    extern __shared__ float smf[];
    float* sdat  = smf + F_SDAT;
    float* swT   = smf + F_SWT;
    float* sbias = smf + F_SBIAS;
    float* ssw   = smf + F_SSW;
    float* ssb   = smf + F_SSB;
    float* srw   = smf + F_SRW;
    float* scoef = smf + F_SCOEF;
    float* sstat = smf + F_SSTAT;
    float* sgam  = smf + F_SGAM;
    float* sbet  = smf + F_SBET;
    float* sfeat = smf + F_SFEAT;
    double* ss   = (double*)(smf + F_TOTAL);
    double* sq   = ss + 256;

    const int tid = threadIdx.x;
    const int wid = tid >> 5, lane = tid & 31;

    // ---------------- phase 0: stage everything into SMEM ----------------
    for (int idx = tid; idx < NB * NC * 3; idx += 256) {
        int b = idx / (NC * 3);
        int r = idx - b * (NC * 3);
        int n = r / 3, c = r - n * 3;
        int sw = n & 4;                          // bank swizzle
        float* db = sdat + b * NC * 8;
        db[n * 8 + sw + c]       = xc[idx];
        db[n * 8 + (sw ^ 4) + c] = yc[idx];
    }
    for (int idx = tid; idx < OC * 18; idx += 256) {
        int o = idx / 18, k = idx - o * 18;
        swT[k * 64 + o] = gw[idx];               // transposed
    }
    if (tid < NB * NBAS * 3) {                   // 120 fourier params (all batches)
        int b = tid / 30, r = tid % 30, k = r / 3, p = r % 3;
        float wstd = 1.0f / (expf(sigma[p]) + EPSV);
        ssw[tid] = expf(mu[p]) + wstd * eps1[(b * NBAS + k) * 3 + p];
        ssb[tid] = 6.283185307179586f * bu[(b * NBAS + k) * 3 + p];
    }
    if (tid >= 128 && tid < 192) sbias[tid - 128] = gb[tid - 128];
    if (tid >= 192 && tid < 202) srw[tid - 192] = rw[tid - 192];
    if (tid >= 208 && tid < 211) {
        int p = tid - 208;
        float inv = 1.0f / (expf(sigma[p]) + EPSV);
        scoef[p] = -0.5f * inv * inv * 1.4426950408889634f;  // fold log2(e)
    }
    if (tid >= 216 && tid < 225) {
        int j = tid - 216;
        int c = j / 3, p = j - c * 3;
        sgam[j] = gamma[p * 3 + c];
        sbet[j] = beta[p * 3 + c];
    }
    __syncthreads();

    // ---------------- phase 1: RBF sums + fourier prior (MUFU-bound) ------
    {
        const float c0 = scoef[0], c1 = scoef[1], c2 = scoef[2];
        const int W = gridDim.x * 8;
        for (int pt = blockIdx.x * 8 + wid; pt < NPT; pt += W) {
            const int b = pt >> 11, g = pt & (NG - 1);
            const float* xgp = &xg[pt * 3];
            const float xg0 = xgp[0], xg1 = xgp[1], xg2 = xgp[2];
            const float* db = sdat + b * NC * 8;

            float h0[9], h1[9];
#pragma unroll
            for (int j = 0; j < 9; j++) { h0[j] = 0.f; h1[j] = 0.f; }

#pragma unroll 4
            for (int it = 0; it < NC / 32; ++it) {
                int n = it * 32 + lane;
                int sw = n & 4;
                float4 v = *reinterpret_cast<const float4*>(&db[n * 8 + sw]);
                float4 u = *reinterpret_cast<const float4*>(&db[n * 8 + (sw ^ 4)]);
                float d0 = v.x - xg0, d1 = v.y - xg1, d2 = v.z - xg2;
                float s0 = d0 * d0, s1 = d1 * d1, s2 = d2 * d2;
                float e;
                e = ex2f(s0 * c0); h0[0] += e; h1[0] = fmaf(e, u.x, h1[0]);
                e = ex2f(s0 * c1); h0[1] += e; h1[1] = fmaf(e, u.x, h1[1]);
                e = ex2f(s0 * c2); h0[2] += e; h1[2] = fmaf(e, u.x, h1[2]);
                e = ex2f(s1 * c0); h0[3] += e; h1[3] = fmaf(e, u.y, h1[3]);
                e = ex2f(s1 * c1); h0[4] += e; h1[4] = fmaf(e, u.y, h1[4]);
                e = ex2f(s1 * c2); h0[5] += e; h1[5] = fmaf(e, u.y, h1[5]);
                e = ex2f(s2 * c0); h0[6] += e; h1[6] = fmaf(e, u.z, h1[6]);
                e = ex2f(s2 * c1); h0[7] += e; h1[7] = fmaf(e, u.z, h1[7]);
                e = ex2f(s2 * c2); h0[8] += e; h1[8] = fmaf(e, u.z, h1[8]);
            }

#pragma unroll
            for (int off = 16; off > 0; off >>= 1) {
#pragma unroll
                for (int j = 0; j < 9; j++) {
                    h0[j] += __shfl_xor_sync(0xffffffffu, h0[j], off);
                    h1[j] += __shfl_xor_sync(0xffffffffu, h1[j], off);
                }
            }

            if (lane < 9) {
                float h0v = 0.f, h1v = 0.f;
                switch (lane) {
                    case 0: h0v = h0[0]; h1v = h1[0]; break;
                    case 1: h0v = h0[1]; h1v = h1[1]; break;
                    case 2: h0v = h0[2]; h1v = h1[2]; break;
                    case 3: h0v = h0[3]; h1v = h1[3]; break;
                    case 4: h0v = h0[4]; h1v = h1[4]; break;
                    case 5: h0v = h0[5]; h1v = h1[5]; break;
                    case 6: h0v = h0[6]; h1v = h1[6]; break;
                    case 7: h0v = h0[7]; h1v = h1[7]; break;
                    case 8: h0v = h0[8]; h1v = h1[8]; break;
                }
                int c = lane / 3;
                int p = lane - c * 3;
                float xgc = (c == 0) ? xg0 : ((c == 1) ? xg1 : xg2);
                float nh1 = h1v / (h0v + EPSV);

                // mul-then-add (no FMA) to match reference fp32 arg exactly
                float fp = 0.f;
                const float* swb = ssw + b * 30;
                const float* sbb = ssb + b * 30;
#pragma unroll
                for (int k = 0; k < NBAS; k++) {
                    float arg = __fadd_rn(__fmul_rn(swb[k * 3 + p], xgc), sbb[k * 3 + p]);
                    fp += srw[k] * cosf(arg);
                }
                fp *= 0.4472135954999579f;        // sqrt(2/10)

                int base = pt * 9 + lane;
                out[OFF_H0 + base] = h0v;
                out[OFF_NH1 + base] = nh1;
                out[OFF_FP + base] = fp;
                g_pos[lane * NPT + pt] = nh1 + fp;  // SoA [chan][b*NG+g]
            }
        }
    }
    __threadfence();
    gridbar();

    // ---------------- phase 2: depthwise convs along g --------------------
    for (int t = blockIdx.x * 256 + tid; t < 9 * NPT; t += gridDim.x * 256) {
        int chan = t / NPT;                       // uniform per warp
        int rem = t - chan * NPT;
        int g = rem & (NG - 1);
        int c = chan / 3, p = chan - c * 3;

        int ksz = (p == 0) ? 3 : ((p == 1) ? 5 : 9);
        int pad = ksz >> 1;
        const float* w  = (p == 0) ? w1 : ((p == 1) ? w2 : w3);
        const float* bb = (p == 0) ? b1 : ((p == 1) ? b2 : b3);

        float acc = bb[c];
        const float* src = &g_pos[t - g];         // row start [chan][b][0]
        for (int tt = 0; tt < ksz; tt++) {
            int gg = g + tt - pad;
            if (gg >= 0 && gg < NG)
                acc = fmaf(src[gg], w[c * ksz + tt], acc);
        }
        g_conv[t] = acc;
    }
    __threadfence();
    gridbar();

    // ---------------- phase 3: BN stats (blocks 0..8, deterministic) ------
    if (blockIdx.x < 9) {
        const int chan = blockIdx.x;
        const float* src = &g_conv[chan * NPT];
        double s4[4] = {0, 0, 0, 0}, q4[4] = {0, 0, 0, 0};
#pragma unroll
        for (int k = 0; k < NPT / 256; k++) {
            double v = (double)src[tid + k * 256];
            s4[k & 3] += v;
            q4[k & 3] = fma(v, v, q4[k & 3]);
        }
        ss[tid] = (s4[0] + s4[1]) + (s4[2] + s4[3]);
        sq[tid] = (q4[0] + q4[1]) + (q4[2] + q4[3]);
        __syncthreads();
        for (int off = 128; off > 0; off >>= 1) {
            if (tid < off) { ss[tid] += ss[tid + off]; sq[tid] += sq[tid + off]; }
            __syncthreads();
        }
        if (tid == 0) {
            double m = ss[0] / (double)NPT;
            double var = sq[0] / (double)NPT - m * m;
            if (var < 0.0) var = 0.0;
            g_stats[chan] = (float)m;
            g_stats[9 + chan] = (float)(1.0 / sqrt(var + (double)BN_EPS));
        }
    }
    __threadfence();
    gridbar();

    // ---------------- phase 4: BN apply + n_f + linear head ---------------
    if (tid < 18) sstat[tid] = g_stats[tid];
    __syncthreads();

    for (int base = blockIdx.x * 32; base < NPT; base += gridDim.x * 32) {
        for (int idx = tid; idx < 288; idx += 256)
            sfeat[(idx / 9) * 19 + (idx % 9)] = out[OFF_H0 + base * 9 + idx];
        for (int idx = tid; idx < 288; idx += 256) {
            int j = idx >> 5, t = idx & 31;
            float x = g_conv[j * NPT + base + t];
            sfeat[t * 19 + 9 + j] = sgam[j] * (x - sstat[j]) * sstat[9 + j] + sbet[j];
        }
        __syncthreads();

        for (int idx = tid; idx < 288; idx += 256)
            out[OFF_NF + base * 9 + idx] = sfeat[(idx / 9) * 19 + 9 + (idx % 9)];

        const int pt = tid >> 3;                  // 0..31
        const int og = (tid & 7) * 8;
        const float* f = &sfeat[pt * 19];
        float acc[8];
#pragma unroll
        for (int oi = 0; oi < 8; oi++) acc[oi] = sbias[og + oi];
#pragma unroll
        for (int k = 0; k < 18; k++) {
            float fv = f[k];
            float4 wa = *reinterpret_cast<const float4*>(&swT[k * 64 + og]);
            float4 wb = *reinterpret_cast<const float4*>(&swT[k * 64 + og + 4]);
            acc[0] = fmaf(fv, wa.x, acc[0]);
            acc[1] = fmaf(fv, wa.y, acc[1]);
            acc[2] = fmaf(fv, wa.z, acc[2]);
            acc[3] = fmaf(fv, wa.w, acc[3]);
            acc[4] = fmaf(fv, wb.x, acc[4]);
            acc[5] = fmaf(fv, wb.y, acc[5]);
            acc[6] = fmaf(fv, wb.z, acc[6]);
            acc[7] = fmaf(fv, wb.w, acc[7]);
        }
        float* yo = &out[OFF_Y + (base + pt) * OC + og];
        *reinterpret_cast<float4*>(yo)     = make_float4(acc[0], acc[1], acc[2], acc[3]);
        *reinterpret_cast<float4*>(yo + 4) = make_float4(acc[4], acc[5], acc[6], acc[7]);
        __syncthreads();
    }
}

// ============================================================
extern "C" void kernel_launch(void* const* d_in, const int* in_sizes, int n_in,
                              void* d_out, int out_size)
{
    const float* xc    = (const float*)d_in[0];
    const float* yc    = (const float*)d_in[1];
    const float* xg    = (const float*)d_in[2];
    const float* sigma = (const float*)d_in[3];
    const float* mu    = (const float*)d_in[4];
    const float* eps1  = (const float*)d_in[5];
    const float* bu    = (const float*)d_in[6];
    const float* rw    = (const float*)d_in[7];
    const float* w1    = (const float*)d_in[8];
    const float* b1    = (const float*)d_in[9];
    const float* w2    = (const float*)d_in[10];
    const float* b2    = (const float*)d_in[11];
    const float* w3    = (const float*)d_in[12];
    const float* b3    = (const float*)d_in[13];
    const float* gamma = (const float*)d_in[14];
    const float* beta  = (const float*)d_in[15];
    const float* gw    = (const float*)d_in[16];
    const float* gb    = (const float*)d_in[17];
    float* out = (float*)d_out;

    int dev = 0;
    cudaGetDevice(&dev);
    int sms = 0;
    cudaDeviceGetAttribute(&sms, cudaDevAttrMultiProcessorCount, dev);
    cudaFuncSetAttribute(fused_all, cudaFuncAttributeMaxDynamicSharedMemorySize, SMEM_BYTES);
    int occ = 0;
    cudaOccupancyMaxActiveBlocksPerMultiprocessor(&occ, fused_all, 256, SMEM_BYTES);
    if (occ < 1) occ = 1;
    if (occ > 2) occ = 2;
    int grid = sms * occ;
    if (grid > 256) grid = 256;          // co-resident (<= sms*occ), cheap barrier

    fused_all<<<grid, 256, SMEM_BYTES>>>(xc, yc, xg, sigma, mu, eps1, bu, rw,
                                         w1, b1, w2, b2, w3, b3,
                                         gamma, beta, gw, gb, out);
}

// round 4
// speedup vs baseline: 1.1910x; 1.1910x over previous
#include <cuda_runtime.h>
#include <cstdint>

// ---------------- problem constants ----------------
#define NB 4
#define NC 512
#define NG 2048
#define CH 3
#define OC 64
#define NBAS 10
#define NPT 8192
#define EPSV 1e-6f
#define BN_EPS 1e-5f

// output layout (float32, concatenated in return order)
#define OFF_Y   0
#define OFF_NF  524288
#define OFF_FP  598016
#define OFF_NH1 671744
#define OFF_H0  745472

// scratch (device globals). SoA: [chan][b*NG+g]
__device__ float g_pos[9 * NPT];
__device__ float g_conv[9 * NPT];
__device__ float g_stats[18];
__device__ unsigned g_barcnt = 0;
__device__ volatile unsigned g_sense = 0;

__device__ __forceinline__ float ex2f(float x) {
    float y;
    asm("ex2.approx.ftz.f32 %0, %1;" : "=f"(y) : "f"(x));
    return y;
}

// ============================================================
// Kernel 1: RBF pairwise sums + fourier prior (unchanged from
//           the 32.8us baseline -- best measured phase-1 config)
// ============================================================
__global__ void __launch_bounds__(256)
k1_rbf(const float* __restrict__ xc, const float* __restrict__ yc,
       const float* __restrict__ xg, const float* __restrict__ sigma,
       const float* __restrict__ mu, const float* __restrict__ eps1,
       const float* __restrict__ bu, const float* __restrict__ rw,
       float* __restrict__ out)
{
    __shared__ float sdat[NC * 8];
    __shared__ float ssw[NBAS * 3];
    __shared__ float ssb[NBAS * 3];
    __shared__ float srw[NBAS];
    __shared__ float scoef[3];

    const int b = blockIdx.y;
    const int tid = threadIdx.x;

    for (int idx = tid; idx < NC * CH; idx += 256) {
        int n = idx / 3, c = idx - n * 3;
        int sw = n & 4;
        sdat[n * 8 + sw + c]        = xc[(b * NC + n) * 3 + c];
        sdat[n * 8 + (sw ^ 4) + c]  = yc[(b * NC + n) * 3 + c];
    }
    if (tid < NBAS * 3) {
        int k = tid / 3, p = tid - k * 3;
        float w_std = 1.0f / (expf(sigma[p]) + EPSV);
        ssw[tid] = expf(mu[p]) + w_std * eps1[(b * NBAS + k) * 3 + p];
        ssb[tid] = 6.283185307179586f * bu[(b * NBAS + k) * 3 + p];
    }
    if (tid >= 32 && tid < 32 + NBAS) srw[tid - 32] = rw[tid - 32];
    if (tid >= 64 && tid < 67) {
        int p = tid - 64;
        float inv = 1.0f / (expf(sigma[p]) + EPSV);
        scoef[p] = -0.5f * inv * inv * 1.4426950408889634f;
    }
    __syncthreads();

    const int wid = tid >> 5, lane = tid & 31;
    const int g = blockIdx.x * 8 + wid;
    const float* xgp = &xg[(b * NG + g) * 3];
    const float xg0 = xgp[0], xg1 = xgp[1], xg2 = xgp[2];
    const float c0 = scoef[0], c1 = scoef[1], c2 = scoef[2];

    float h0[9], h1[9];
#pragma unroll
    for (int j = 0; j < 9; j++) { h0[j] = 0.f; h1[j] = 0.f; }

#pragma unroll 4
    for (int it = 0; it < NC / 32; ++it) {
        int n = it * 32 + lane;
        int sw = n & 4;
        float4 v = *reinterpret_cast<const float4*>(&sdat[n * 8 + sw]);
        float4 u = *reinterpret_cast<const float4*>(&sdat[n * 8 + (sw ^ 4)]);
        float d0 = v.x - xg0, d1 = v.y - xg1, d2 = v.z - xg2;
        float s0 = d0 * d0, s1 = d1 * d1, s2 = d2 * d2;
        float e;
        e = ex2f(s0 * c0); h0[0] += e; h1[0] = fmaf(e, u.x, h1[0]);
        e = ex2f(s0 * c1); h0[1] += e; h1[1] = fmaf(e, u.x, h1[1]);
        e = ex2f(s0 * c2); h0[2] += e; h1[2] = fmaf(e, u.x, h1[2]);
        e = ex2f(s1 * c0); h0[3] += e; h1[3] = fmaf(e, u.y, h1[3]);
        e = ex2f(s1 * c1); h0[4] += e; h1[4] = fmaf(e, u.y, h1[4]);
        e = ex2f(s1 * c2); h0[5] += e; h1[5] = fmaf(e, u.y, h1[5]);
        e = ex2f(s2 * c0); h0[6] += e; h1[6] = fmaf(e, u.z, h1[6]);
        e = ex2f(s2 * c1); h0[7] += e; h1[7] = fmaf(e, u.z, h1[7]);
        e = ex2f(s2 * c2); h0[8] += e; h1[8] = fmaf(e, u.z, h1[8]);
    }

#pragma unroll
    for (int off = 16; off > 0; off >>= 1) {
#pragma unroll
        for (int j = 0; j < 9; j++) {
            h0[j] += __shfl_xor_sync(0xffffffffu, h0[j], off);
            h1[j] += __shfl_xor_sync(0xffffffffu, h1[j], off);
        }
    }

    if (lane < 9) {
        float h0v = 0.f, h1v = 0.f;
        switch (lane) {
            case 0: h0v = h0[0]; h1v = h1[0]; break;
            case 1: h0v = h0[1]; h1v = h1[1]; break;
            case 2: h0v = h0[2]; h1v = h1[2]; break;
            case 3: h0v = h0[3]; h1v = h1[3]; break;
            case 4: h0v = h0[4]; h1v = h1[4]; break;
            case 5: h0v = h0[5]; h1v = h1[5]; break;
            case 6: h0v = h0[6]; h1v = h1[6]; break;
            case 7: h0v = h0[7]; h1v = h1[7]; break;
            case 8: h0v = h0[8]; h1v = h1[8]; break;
        }
        int c = lane / 3;
        int p = lane - c * 3;
        float xgc = (c == 0) ? xg0 : ((c == 1) ? xg1 : xg2);
        float nh1 = h1v / (h0v + EPSV);

        float fp = 0.f;
#pragma unroll
        for (int k = 0; k < NBAS; k++) {
            float arg = __fadd_rn(__fmul_rn(ssw[k * 3 + p], xgc), ssb[k * 3 + p]);
            fp += srw[k] * cosf(arg);
        }
        fp *= 0.4472135954999579f;

        int pt = b * NG + g;
        int base = pt * 9 + lane;
        out[OFF_H0 + base] = h0v;
        out[OFF_NH1 + base] = nh1;
        out[OFF_FP + base] = fp;
        g_pos[lane * NPT + pt] = nh1 + fp;
    }
}

// ============================================================
// k_rest: persistent kernel = conv -> BN stats -> BN + head.
//         148 blocks x 512 threads, 2 grid barriers.
// ============================================================
#define RG 148          // grid (one block per SM; co-resident)
#define RT 512          // threads per block

__device__ __forceinline__ void gridbar() {
    __syncthreads();
    if (threadIdx.x == 0) {
        unsigned s = g_sense;
        __threadfence();
        if (atomicAdd(&g_barcnt, 1u) == gridDim.x - 1) {
            g_barcnt = 0;
            __threadfence();
            g_sense = s + 1;
        } else {
            while (g_sense == s) { }
        }
        __threadfence();
    }
    __syncthreads();
}

__global__ void __launch_bounds__(RT, 1)
k_rest(const float* __restrict__ w1, const float* __restrict__ b1,
       const float* __restrict__ w2, const float* __restrict__ b2,
       const float* __restrict__ w3, const float* __restrict__ b3,
       const float* __restrict__ gamma, const float* __restrict__ beta,
       const float* __restrict__ gw, const float* __restrict__ gb,
       float* __restrict__ out)
{
    __shared__ float swT[18 * 64];
    __shared__ float sbias[OC];
    __shared__ float sstat[18];
    __shared__ float sgam[9], sbet[9];
    __shared__ float sfeat[64 * 19];
    __shared__ double sred[RT * 2];

    const int tid = threadIdx.x;

    // stage head weights / bn params (overlaps phase A)
    for (int idx = tid; idx < OC * 18; idx += RT) {
        int o = idx / 18, k = idx - o * 18;
        swT[k * 64 + o] = gw[idx];
    }
    if (tid < OC) sbias[tid] = gb[tid];
    if (tid >= 64 && tid < 73) {
        int j = tid - 64;
        int c = j / 3, p = j - c * 3;
        sgam[j] = gamma[p * 3 + c];
        sbet[j] = beta[p * 3 + c];
    }

    // ---------------- phase A: depthwise convs ----------------
    {
        int t = blockIdx.x * RT + tid;
        if (t < 9 * NPT) {
            int chan = t / NPT;
            int rem = t - chan * NPT;
            int g = rem & (NG - 1);
            int c = chan / 3, p = chan - c * 3;

            int ksz = (p == 0) ? 3 : ((p == 1) ? 5 : 9);
            int pad = ksz >> 1;
            const float* w  = (p == 0) ? w1 : ((p == 1) ? w2 : w3);
            const float* bb = (p == 0) ? b1 : ((p == 1) ? b2 : b3);

            float acc = bb[c];
            const float* src = &g_pos[t - g];
            for (int tt = 0; tt < ksz; tt++) {
                int gg = g + tt - pad;
                if (gg >= 0 && gg < NG)
                    acc = fmaf(src[gg], w[c * ksz + tt], acc);
            }
            g_conv[t] = acc;
        }
    }
    __threadfence();
    gridbar();

    // ---------------- phase B: BN stats (blocks 0..8) ----------
    if (blockIdx.x < 9) {
        const int chan = blockIdx.x;
        const float* src = &g_conv[chan * NPT];
        double s4[4] = {0, 0, 0, 0}, q4[4] = {0, 0, 0, 0};
#pragma unroll
        for (int k = 0; k < NPT / RT; k++) {          // 16 iters
            double v = (double)src[tid + k * RT];
            s4[k & 3] += v;
            q4[k & 3] = fma(v, v, q4[k & 3]);
        }
        sred[tid]      = (s4[0] + s4[1]) + (s4[2] + s4[3]);
        sred[RT + tid] = (q4[0] + q4[1]) + (q4[2] + q4[3]);
        __syncthreads();
        for (int off = RT / 2; off > 0; off >>= 1) {
            if (tid < off) {
                sred[tid]      += sred[tid + off];
                sred[RT + tid] += sred[RT + tid + off];
            }
            __syncthreads();
        }
        if (tid == 0) {
            double m = sred[0] / (double)NPT;
            double var = sred[RT] / (double)NPT - m * m;
            if (var < 0.0) var = 0.0;
            g_stats[chan] = (float)m;
            g_stats[9 + chan] = (float)(1.0 / sqrt(var + (double)BN_EPS));
        }
    }
    __threadfence();
    gridbar();

    // ---------------- phase C: BN apply + n_f + head -----------
    if (tid < 18) sstat[tid] = g_stats[tid];
    __syncthreads();

    for (int base = blockIdx.x * 64; base < NPT; base += RG * 64) {
        for (int idx = tid; idx < 576; idx += RT)
            sfeat[(idx / 9) * 19 + (idx % 9)] = out[OFF_H0 + base * 9 + idx];
        for (int idx = tid; idx < 576; idx += RT) {
            int j = idx >> 6, t = idx & 63;           // channel, point-in-block
            float x = g_conv[j * NPT + base + t];
            sfeat[t * 19 + 9 + j] = sgam[j] * (x - sstat[j]) * sstat[9 + j] + sbet[j];
        }
        __syncthreads();

        for (int idx = tid; idx < 576; idx += RT)
            out[OFF_NF + base * 9 + idx] = sfeat[(idx / 9) * 19 + 9 + (idx % 9)];

        const int pt = tid >> 3;                      // 0..63
        const int og = (tid & 7) * 8;
        const float* f = &sfeat[pt * 19];
        float acc[8];
#pragma unroll
        for (int oi = 0; oi < 8; oi++) acc[oi] = sbias[og + oi];
#pragma unroll
        for (int k = 0; k < 18; k++) {
            float fv = f[k];
            float4 wa = *reinterpret_cast<const float4*>(&swT[k * 64 + og]);
            float4 wb = *reinterpret_cast<const float4*>(&swT[k * 64 + og + 4]);
            acc[0] = fmaf(fv, wa.x, acc[0]);
            acc[1] = fmaf(fv, wa.y, acc[1]);
            acc[2] = fmaf(fv, wa.z, acc[2]);
            acc[3] = fmaf(fv, wa.w, acc[3]);
            acc[4] = fmaf(fv, wb.x, acc[4]);
            acc[5] = fmaf(fv, wb.y, acc[5]);
            acc[6] = fmaf(fv, wb.z, acc[6]);
            acc[7] = fmaf(fv, wb.w, acc[7]);
        }
        float* yo = &out[OFF_Y + (base + pt) * OC + og];
        *reinterpret_cast<float4*>(yo)     = make_float4(acc[0], acc[1], acc[2], acc[3]);
        *reinterpret_cast<float4*>(yo + 4) = make_float4(acc[4], acc[5], acc[6], acc[7]);
        __syncthreads();
    }
}

// ============================================================
extern "C" void kernel_launch(void* const* d_in, const int* in_sizes, int n_in,
                              void* d_out, int out_size)
{
    const float* xc    = (const float*)d_in[0];
    const float* yc    = (const float*)d_in[1];
    const float* xg    = (const float*)d_in[2];
    const float* sigma = (const float*)d_in[3];
    const float* mu    = (const float*)d_in[4];
    const float* eps1  = (const float*)d_in[5];
    const float* bu    = (const float*)d_in[6];
    const float* rw    = (const float*)d_in[7];
    const float* w1    = (const float*)d_in[8];
    const float* b1    = (const float*)d_in[9];
    const float* w2    = (const float*)d_in[10];
    const float* b2    = (const float*)d_in[11];
    const float* w3    = (const float*)d_in[12];
    const float* b3    = (const float*)d_in[13];
    const float* gamma = (const float*)d_in[14];
    const float* beta  = (const float*)d_in[15];
    const float* gw    = (const float*)d_in[16];
    const float* gb    = (const float*)d_in[17];
    float* out = (float*)d_out;

    dim3 grid1(NG / 8, NB);
    k1_rbf<<<grid1, 256>>>(xc, yc, xg, sigma, mu, eps1, bu, rw, out);
    k_rest<<<RG, RT>>>(w1, b1, w2, b2, w3, b3, gamma, beta, gw, gb, out);
}